// round 1
// baseline (speedup 1.0000x reference)
#include <cuda_runtime.h>

#define N_NODES 20000
#define N_EDGES 240000
#define IN_DIM  20
#define SH_DIM  16
#define OUT_DIM 360   // 20 (mlp) + 20 (sender sum) + 320 (tensor product)

// ---- scratch (no allocations allowed) ----
__device__ int g_count[N_NODES];
__device__ int g_start[N_NODES + 1];
__device__ int g_cursor[N_NODES];
__device__ int g_edge_row[N_EDGES];

// ============================================================================
// K0: per-node MLP (output cols 0..19) + zero the degree histogram
// ============================================================================
__global__ void k_mlp_zero(const float* __restrict__ x,
                           const float* __restrict__ Wpre,  const float* __restrict__ bpre,
                           const float* __restrict__ Wpost, const float* __restrict__ bpost,
                           const float* __restrict__ Wsc,   const float* __restrict__ bsc,
                           float* __restrict__ out)
{
    __shared__ float sWpre[400], sWpost[400], sWsc[400], sb[60];
    for (int i = threadIdx.x; i < 400; i += blockDim.x) {
        sWpre[i]  = Wpre[i];
        sWpost[i] = Wpost[i];
        sWsc[i]   = Wsc[i];
    }
    for (int i = threadIdx.x; i < 20; i += blockDim.x) {
        sb[i]      = bpre[i];
        sb[20 + i] = bpost[i];
        sb[40 + i] = bsc[i];
    }
    __syncthreads();

    int n = blockIdx.x * blockDim.x + threadIdx.x;
    if (n >= N_NODES) return;

    g_count[n] = 0;

    float xr[IN_DIM];
#pragma unroll
    for (int k = 0; k < IN_DIM; k++) xr[k] = x[n * IN_DIM + k];

    // pre = relu(x @ Wpre^T + bpre)   (DENOM = 1.0)
    float pre[IN_DIM];
#pragma unroll
    for (int i = 0; i < IN_DIM; i++) {
        float a = sb[i];
#pragma unroll
        for (int k = 0; k < IN_DIM; k++) a = fmaf(xr[k], sWpre[i * IN_DIM + k], a);
        pre[i] = fmaxf(a, 0.0f);
    }

    // out = x @ Wsc^T + bsc + (pre @ Wpost^T + bpost)
#pragma unroll
    for (int i = 0; i < IN_DIM; i++) {
        float a = sb[20 + i] + sb[40 + i];
#pragma unroll
        for (int k = 0; k < IN_DIM; k++) {
            a = fmaf(pre[k], sWpost[i * IN_DIM + k], a);
            a = fmaf(xr[k],  sWsc[i * IN_DIM + k],  a);
        }
        out[n * OUT_DIM + i] = a;
    }
}

// ============================================================================
// K1: histogram of destination (col) degrees
// ============================================================================
__global__ void k_hist(const int* __restrict__ ei)
{
    int e = blockIdx.x * blockDim.x + threadIdx.x;
    if (e < N_EDGES) atomicAdd(&g_count[ei[N_EDGES + e]], 1);
}

// ============================================================================
// K2: exclusive scan of counts -> g_start, g_cursor  (single block, 1024 thr,
//     20 contiguous elements per thread, Hillis–Steele over per-thread sums)
// ============================================================================
__global__ void k_scan()
{
    __shared__ int sdata[1024];
    const int t = threadIdx.x;
    const int base = t * 20;

    int c[20];
    int s = 0;
#pragma unroll
    for (int k = 0; k < 20; k++) {
        int i = base + k;
        c[k] = (i < N_NODES) ? g_count[i] : 0;
        s += c[k];
    }
    sdata[t] = s;
    __syncthreads();
#pragma unroll
    for (int off = 1; off < 1024; off <<= 1) {
        int v = (t >= off) ? sdata[t - off] : 0;
        __syncthreads();
        sdata[t] += v;
        __syncthreads();
    }
    int run = (t == 0) ? 0 : sdata[t - 1];
#pragma unroll
    for (int k = 0; k < 20; k++) {
        int i = base + k;
        if (i < N_NODES) {
            g_start[i]  = run;
            g_cursor[i] = run;
        }
        run += c[k];
    }
    if (t == 1023) g_start[N_NODES] = sdata[1023];
}

// ============================================================================
// K3: scatter edge row-ids into destination-sorted order
// ============================================================================
__global__ void k_scatter(const int* __restrict__ ei)
{
    int e = blockIdx.x * blockDim.x + threadIdx.x;
    if (e >= N_EDGES) return;
    int c = ei[N_EDGES + e];
    int slot = atomicAdd(&g_cursor[c], 1);
    g_edge_row[slot] = ei[e];
}

// ============================================================================
// K4: gather-aggregate — one warp per destination node.
//     lane i < 20 owns sender channel i: acc_s = sum s_i, acc[j] = sum s_i*sh_j
// ============================================================================
__global__ void k_aggr(const float* __restrict__ x,
                       const float* __restrict__ pos,
                       float* __restrict__ out)
{
    const int warp = (blockIdx.x * blockDim.x + threadIdx.x) >> 5;
    const int lane = threadIdx.x & 31;
    if (warp >= N_NODES) return;
    const int n = warp;

    const int s0 = g_start[n];
    const int s1 = g_start[n + 1];

    const float pnx = pos[n * 3 + 0];
    const float pny = pos[n * 3 + 1];
    const float pnz = pos[n * 3 + 2];

    float accS = 0.0f;
    float acc[SH_DIM];
#pragma unroll
    for (int j = 0; j < SH_DIM; j++) acc[j] = 0.0f;

    for (int slot = s0; slot < s1; slot++) {
        int r = g_edge_row[slot];                     // broadcast (uniform in warp)
        float rx = pnx - pos[r * 3 + 0];              // rel = pos[col] - pos[row]
        float ry = pny - pos[r * 3 + 1];
        float rz = pnz - pos[r * 3 + 2];
        float inv = rsqrtf(fmaf(rx, rx, fmaf(ry, ry, fmaf(rz, rz, 1e-12f))));
        float X = rx * inv, Y = ry * inv, Z = rz * inv;
        float X2 = X * X, Y2 = Y * Y, Z2 = Z * Z;

        float sh[SH_DIM];
        sh[0]  = 0.28209479177387814f;
        sh[1]  = 0.4886025119029199f * Y;
        sh[2]  = 0.4886025119029199f * Z;
        sh[3]  = 0.4886025119029199f * X;
        sh[4]  = 1.0925484305920792f * X * Y;
        sh[5]  = 1.0925484305920792f * Y * Z;
        sh[6]  = 0.31539156525252005f * (3.0f * Z2 - 1.0f);
        sh[7]  = 1.0925484305920792f * X * Z;
        sh[8]  = 0.5462742152960396f * (X2 - Y2);
        sh[9]  = 0.5900435899266435f * Y * (3.0f * X2 - Y2);
        sh[10] = 2.890611442640554f  * X * Y * Z;
        sh[11] = 0.4570457994644658f * Y * (5.0f * Z2 - 1.0f);
        sh[12] = 0.3731763325901154f * Z * (5.0f * Z2 - 3.0f);
        sh[13] = 0.4570457994644658f * X * (5.0f * Z2 - 1.0f);
        sh[14] = 1.445305721320277f  * Z * (X2 - Y2);
        sh[15] = 0.5900435899266435f * X * (X2 - 3.0f * Y2);

        float s = (lane < IN_DIM) ? x[r * IN_DIM + lane] : 0.0f;  // coalesced 80B gather
        accS += s;
#pragma unroll
        for (int j = 0; j < SH_DIM; j++) acc[j] = fmaf(s, sh[j], acc[j]);
    }

    if (lane < IN_DIM) {
        float* base = out + n * OUT_DIM;
        base[20 + lane] = accS;                       // sender sum, cols 20..39
        float4* p = (float4*)(base + 40 + lane * SH_DIM);  // tp, cols 40..359
        p[0] = make_float4(acc[0],  acc[1],  acc[2],  acc[3]);
        p[1] = make_float4(acc[4],  acc[5],  acc[6],  acc[7]);
        p[2] = make_float4(acc[8],  acc[9],  acc[10], acc[11]);
        p[3] = make_float4(acc[12], acc[13], acc[14], acc[15]);
    }
}

// ============================================================================
extern "C" void kernel_launch(void* const* d_in, const int* in_sizes, int n_in,
                              void* d_out, int out_size)
{
    const float* x     = (const float*)d_in[0];
    const float* pos   = (const float*)d_in[1];
    const int*   ei    = (const int*)  d_in[2];
    const float* Wpre  = (const float*)d_in[3];
    const float* bpre  = (const float*)d_in[4];
    const float* Wpost = (const float*)d_in[5];
    const float* bpost = (const float*)d_in[6];
    const float* Wsc   = (const float*)d_in[7];
    const float* bsc   = (const float*)d_in[8];
    float* out = (float*)d_out;

    k_mlp_zero<<<(N_NODES + 255) / 256, 256>>>(x, Wpre, bpre, Wpost, bpost, Wsc, bsc, out);
    k_hist<<<(N_EDGES + 255) / 256, 256>>>(ei);
    k_scan<<<1, 1024>>>();
    k_scatter<<<(N_EDGES + 255) / 256, 256>>>(ei);
    k_aggr<<<(N_NODES * 32 + 255) / 256, 256>>>(x, pos, out);
}